// round 2
// baseline (speedup 1.0000x reference)
#include <cuda_runtime.h>
#include <cuda_bf16.h>

#define N_NODES   8192
#define K         32
#define CUTOFF2   100.0f
#define CAND      128          // max candidates per node (graph size <= ~60 w.h.p.)
#define WPB       8            // warps per block

__global__ __launch_bounds__(WPB * 32)
void radius_graph_kernel(const float* __restrict__ pos,
                         const int* __restrict__ batch,
                         float* __restrict__ out) {
    __shared__ float s_d2[WPB][CAND];
    __shared__ int   s_idx[WPB][CAND];
    __shared__ int   s_cnt[WPB];

    const int w    = threadIdx.x >> 5;
    const int lane = threadIdx.x & 31;
    const int i    = blockIdx.x * WPB + w;
    if (i >= N_NODES) return;

    if (lane == 0) s_cnt[w] = 0;
    __syncwarp();

    // ---- segment [seg_lo, seg_hi) of this node's graph (batch is sorted int32) ----
    const int g = batch[i];
    int lo = 0, hi = N_NODES;
    while (lo < hi) { int mid = (lo + hi) >> 1; if (batch[mid] < g) lo = mid + 1; else hi = mid; }
    const int seg_lo = lo;
    hi = N_NODES;
    while (lo < hi) { int mid = (lo + hi) >> 1; if (batch[mid] <= g) lo = mid + 1; else hi = mid; }
    const int seg_hi = lo;

    const float xi = pos[3 * i + 0];
    const float yi = pos[3 * i + 1];
    const float zi = pos[3 * i + 2];
    // sq exactly as jnp.sum(pos*pos, -1): (x*x + y*y) + z*z, no FMA contraction
    const float sqi = __fadd_rn(__fadd_rn(__fmul_rn(xi, xi), __fmul_rn(yi, yi)),
                                __fmul_rn(zi, zi));

    // ---- gather valid candidates ----
    for (int j = seg_lo + lane; j < seg_hi; j += 32) {
        if (j == i) continue;
        const float xj = pos[3 * j + 0];
        const float yj = pos[3 * j + 1];
        const float zj = pos[3 * j + 2];
        const float sqj = __fadd_rn(__fadd_rn(__fmul_rn(xj, xj), __fmul_rn(yj, yj)),
                                    __fmul_rn(zj, zj));
        const float dot = __fadd_rn(__fadd_rn(__fmul_rn(xi, xj), __fmul_rn(yi, yj)),
                                    __fmul_rn(zi, zj));
        // d2 = max(sqi + sqj - 2*dot, 0) with the reference's association
        float d2 = __fsub_rn(__fadd_rn(sqi, sqj), __fmul_rn(2.0f, dot));
        d2 = fmaxf(d2, 0.0f);
        if (d2 <= CUTOFF2) {
            int p = atomicAdd(&s_cnt[w], 1);
            if (p < CAND) { s_d2[w][p] = d2; s_idx[w][p] = j; }
        }
    }
    __syncwarp();
    int C = s_cnt[w];
    if (C > CAND) C = CAND;

    const int NK = N_NODES * K;
    float* __restrict__ out_row = out;
    float* __restrict__ out_col = out + NK;
    float* __restrict__ out_w   = out + 2 * NK;
    float* __restrict__ out_m   = out + 3 * NK;
    const int base = i * K;

    // row is always i; padded slots (rank >= min(C,K)) get col=i, w=0, m=0
    out_row[base + lane] = (float)i;
    const int Cc = C < K ? C : K;
    if (lane >= Cc) {
        out_col[base + lane] = (float)i;
        out_w  [base + lane] = 0.0f;
        out_m  [base + lane] = 0.0f;
    }

    // ---- rank each candidate by (d2 asc, idx asc); write the top-K slots ----
    for (int c = lane; c < C; c += 32) {
        const float d2c = s_d2[w][c];
        const int   jc  = s_idx[w][c];
        int rank = 0;
        for (int m = 0; m < C; m++) {
            const float d2m = s_d2[w][m];
            rank += (d2m < d2c) || (d2m == d2c && s_idx[w][m] < jc);
        }
        if (rank < K) {
            const float dx = xi - pos[3 * jc + 0];
            const float dy = yi - pos[3 * jc + 1];
            const float dz = zi - pos[3 * jc + 2];
            const float wgt = sqrtf(dx * dx + dy * dy + dz * dz);
            out_col[base + rank] = (float)jc;
            out_w  [base + rank] = wgt;
            out_m  [base + rank] = 1.0f;
        }
    }
}

extern "C" void kernel_launch(void* const* d_in, const int* in_sizes, int n_in,
                              void* d_out, int out_size) {
    const float* pos   = (const float*)d_in[0];
    const int*   batch = (const int*)d_in[1];
    float*       out   = (float*)d_out;

    const int blocks = N_NODES / WPB;   // 1024
    radius_graph_kernel<<<blocks, WPB * 32>>>(pos, batch, out);
}

// round 3
// speedup vs baseline: 1.6911x; 1.6911x over previous
#include <cuda_runtime.h>
#include <cuda_bf16.h>

#define N_NODES   8192
#define K         32
#define CUTOFF2   100.0f
#define CAND      128          // max candidates per node (graph size <= ~60 w.h.p.)
#define WPB       8            // warps per block

__global__ __launch_bounds__(WPB * 32)
void radius_graph_kernel(const float* __restrict__ pos,
                         const int* __restrict__ batch,
                         float* __restrict__ out) {
    __shared__ float s_d2[WPB][CAND];
    __shared__ int   s_idx[WPB][CAND];

    const int w    = threadIdx.x >> 5;
    const int lane = threadIdx.x & 31;
    const int i    = blockIdx.x * WPB + w;

    const int g = batch[i];

    // ---- find segment [seg_lo, seg_hi) by warp ballot scan (batch sorted) ----
    int seg_lo;
    {
        int base = 0;
        for (;;) {
            const int j = i - 1 - base - lane;              // increasing distance by lane
            const bool off = (j < 0) || (batch[j] != g);
            const unsigned m = __ballot_sync(0xffffffffu, off);
            if (m) { seg_lo = i - base - (__ffs(m) - 1); break; }
            base += 32;
        }
    }
    int seg_hi;
    {
        int base = 0;
        for (;;) {
            const int j = i + 1 + base + lane;
            const bool off = (j >= N_NODES) || (batch[j] != g);
            const unsigned m = __ballot_sync(0xffffffffu, off);
            if (m) { seg_hi = i + 1 + base + (__ffs(m) - 1); break; }
            base += 32;
        }
    }

    const float xi = pos[3 * i + 0];
    const float yi = pos[3 * i + 1];
    const float zi = pos[3 * i + 2];
    // sq exactly as jnp.sum(pos*pos, -1): (x*x + y*y) + z*z, no FMA contraction
    const float sqi = __fadd_rn(__fadd_rn(__fmul_rn(xi, xi), __fmul_rn(yi, yi)),
                                __fmul_rn(zi, zi));

    // ---- gather valid candidates via ballot-prefix append (no atomics) ----
    int cnt = 0;                                            // lane-uniform
    for (int jb = seg_lo; jb < seg_hi && cnt < CAND; jb += 32) {
        const int j = jb + lane;
        bool valid = (j < seg_hi) && (j != i);
        float d2 = 0.0f;
        if (valid) {
            const float xj = pos[3 * j + 0];
            const float yj = pos[3 * j + 1];
            const float zj = pos[3 * j + 2];
            const float sqj = __fadd_rn(__fadd_rn(__fmul_rn(xj, xj), __fmul_rn(yj, yj)),
                                        __fmul_rn(zj, zj));
            const float dot = __fadd_rn(__fadd_rn(__fmul_rn(xi, xj), __fmul_rn(yi, yj)),
                                        __fmul_rn(zi, zj));
            d2 = __fsub_rn(__fadd_rn(sqi, sqj), __fmul_rn(2.0f, dot));
            d2 = fmaxf(d2, 0.0f);
            valid = (d2 <= CUTOFF2);
        }
        const unsigned m = __ballot_sync(0xffffffffu, valid);
        if (valid) {
            const int pos_c = cnt + __popc(m & ((1u << lane) - 1u));
            if (pos_c < CAND) { s_d2[w][pos_c] = d2; s_idx[w][pos_c] = j; }
        }
        cnt += __popc(m);
    }
    __syncwarp();
    const int C = cnt < CAND ? cnt : CAND;

    const int NK = N_NODES * K;
    float* __restrict__ out_row = out;
    float* __restrict__ out_col = out + NK;
    float* __restrict__ out_w   = out + 2 * NK;
    float* __restrict__ out_m   = out + 3 * NK;
    const int base = i * K;

    // row is always i; padded slots (rank >= min(C,K)) get col=i, w=0, m=0
    out_row[base + lane] = (float)i;
    const int Cc = C < K ? C : K;
    if (lane >= Cc) {
        out_col[base + lane] = (float)i;
        out_w  [base + lane] = 0.0f;
        out_m  [base + lane] = 0.0f;
    }

    // ---- rank each candidate by (d2 asc, idx asc); write the top-K slots ----
    for (int c = lane; c < C; c += 32) {
        const float d2c = s_d2[w][c];
        const int   jc  = s_idx[w][c];
        int rank = 0;
        for (int m = 0; m < C; m++) {
            const float d2m = s_d2[w][m];
            rank += (d2m < d2c) || (d2m == d2c && s_idx[w][m] < jc);
        }
        if (rank < K) {
            const float dx = xi - pos[3 * jc + 0];
            const float dy = yi - pos[3 * jc + 1];
            const float dz = zi - pos[3 * jc + 2];
            const float wgt = sqrtf(dx * dx + dy * dy + dz * dz);
            out_col[base + rank] = (float)jc;
            out_w  [base + rank] = wgt;
            out_m  [base + rank] = 1.0f;
        }
    }
}

extern "C" void kernel_launch(void* const* d_in, const int* in_sizes, int n_in,
                              void* d_out, int out_size) {
    const float* pos   = (const float*)d_in[0];
    const int*   batch = (const int*)d_in[1];
    float*       out   = (float*)d_out;

    const int blocks = N_NODES / WPB;   // 1024
    radius_graph_kernel<<<blocks, WPB * 32>>>(pos, batch, out);
}

// round 4
// speedup vs baseline: 2.2828x; 1.3499x over previous
#include <cuda_runtime.h>
#include <cuda_bf16.h>

#define N_NODES   8192
#define K         32
#define CUTOFF2   100.0f
#define CAND      128          // max candidates per node (graph size <= ~60 w.h.p.)
#define WPB       4            // warps per block

__global__ __launch_bounds__(WPB * 32)
void radius_graph_kernel(const float* __restrict__ pos,
                         const int* __restrict__ batch,
                         float* __restrict__ out) {
    __shared__ unsigned long long s_key[WPB][CAND];   // (d2 bits << 32) | idx

    const int w    = threadIdx.x >> 5;
    const int lane = threadIdx.x & 31;
    const int i    = blockIdx.x * WPB + w;

    const int g = batch[i];

    // ---- find segment [seg_lo, seg_hi) by warp ballot scan (batch sorted) ----
    int seg_lo;
    {
        int base = 0;
        for (;;) {
            const int j = i - 1 - base - lane;              // increasing distance by lane
            const bool off = (j < 0) || (batch[j] != g);
            const unsigned m = __ballot_sync(0xffffffffu, off);
            if (m) { seg_lo = i - base - (__ffs(m) - 1); break; }
            base += 32;
        }
    }
    int seg_hi;
    {
        int base = 0;
        for (;;) {
            const int j = i + 1 + base + lane;
            const bool off = (j >= N_NODES) || (batch[j] != g);
            const unsigned m = __ballot_sync(0xffffffffu, off);
            if (m) { seg_hi = i + 1 + base + (__ffs(m) - 1); break; }
            base += 32;
        }
    }

    const float xi = pos[3 * i + 0];
    const float yi = pos[3 * i + 1];
    const float zi = pos[3 * i + 2];
    // sq exactly as jnp.sum(pos*pos, -1): (x*x + y*y) + z*z, no FMA contraction
    const float sqi = __fadd_rn(__fadd_rn(__fmul_rn(xi, xi), __fmul_rn(yi, yi)),
                                __fmul_rn(zi, zi));

    // ---- gather valid candidates via ballot-prefix append (no atomics) ----
    int cnt = 0;                                            // lane-uniform
    for (int jb = seg_lo; jb < seg_hi && cnt < CAND; jb += 32) {
        const int j = jb + lane;
        bool valid = (j < seg_hi) && (j != i);
        float d2 = 0.0f;
        if (valid) {
            const float xj = pos[3 * j + 0];
            const float yj = pos[3 * j + 1];
            const float zj = pos[3 * j + 2];
            const float sqj = __fadd_rn(__fadd_rn(__fmul_rn(xj, xj), __fmul_rn(yj, yj)),
                                        __fmul_rn(zj, zj));
            const float dot = __fadd_rn(__fadd_rn(__fmul_rn(xi, xj), __fmul_rn(yi, yj)),
                                        __fmul_rn(zi, zj));
            d2 = __fsub_rn(__fadd_rn(sqi, sqj), __fmul_rn(2.0f, dot));
            d2 = fmaxf(d2, 0.0f);
            valid = (d2 <= CUTOFF2);
        }
        const unsigned m = __ballot_sync(0xffffffffu, valid);
        if (valid) {
            const int pos_c = cnt + __popc(m & ((1u << lane) - 1u));
            if (pos_c < CAND) {
                s_key[w][pos_c] = ((unsigned long long)__float_as_uint(d2) << 32)
                                  | (unsigned)j;
            }
        }
        cnt += __popc(m);
    }
    __syncwarp();
    const int C = cnt < CAND ? cnt : CAND;

    const int NK = N_NODES * K;
    float* __restrict__ out_row = out;
    float* __restrict__ out_col = out + NK;
    float* __restrict__ out_w   = out + 2 * NK;
    float* __restrict__ out_m   = out + 3 * NK;
    const int base = i * K;

    // row is always i; padded slots (rank >= min(C,K)) get col=i, w=0, m=0
    out_row[base + lane] = (float)i;
    const int Cc = C < K ? C : K;
    if (lane >= Cc) {
        out_col[base + lane] = (float)i;
        out_w  [base + lane] = 0.0f;
        out_m  [base + lane] = 0.0f;
    }

    // ---- rank candidates by 64-bit key (d2 asc, idx asc); write top-K slots ----
    for (int c = lane; c < C; c += 32) {
        const unsigned long long kc = s_key[w][c];
        int rank = 0;
        #pragma unroll 4
        for (int m = 0; m < C; m++) {
            rank += (s_key[w][m] < kc);
        }
        if (rank < K) {
            const float d2c = __uint_as_float((unsigned)(kc >> 32));
            const int   jc  = (int)(unsigned)(kc & 0xffffffffu);
            out_col[base + rank] = (float)jc;
            out_w  [base + rank] = sqrtf(d2c);
            out_m  [base + rank] = 1.0f;
        }
    }
}

extern "C" void kernel_launch(void* const* d_in, const int* in_sizes, int n_in,
                              void* d_out, int out_size) {
    const float* pos   = (const float*)d_in[0];
    const int*   batch = (const int*)d_in[1];
    float*       out   = (float*)d_out;

    const int blocks = N_NODES / WPB;   // 2048
    radius_graph_kernel<<<blocks, WPB * 32>>>(pos, batch, out);
}

// round 5
// speedup vs baseline: 2.3234x; 1.0178x over previous
#include <cuda_runtime.h>
#include <cuda_bf16.h>

#define N_NODES   8192
#define K         32
#define CUTOFF2   100.0f
#define CAND      128          // max candidates per node (graph size <= ~60 w.h.p.)
#define WPB       2            // warps per block (small blocks -> less tail imbalance)

__global__ __launch_bounds__(WPB * 32)
void radius_graph_kernel(const float* __restrict__ pos,
                         const int* __restrict__ batch,
                         float* __restrict__ out) {
    __shared__ unsigned long long s_key[WPB][CAND];   // (d2 bits << 32) | idx

    const int w    = threadIdx.x >> 5;
    const int lane = threadIdx.x & 31;
    const int i    = blockIdx.x * WPB + w;

    const int g = batch[i];

    // ---- fused bidirectional segment scan: both directions' loads in flight ----
    int seg_lo = -1, seg_hi = -1;
    for (int base = 0; seg_lo < 0 || seg_hi < 0; base += 32) {
        const int jl = i - 1 - base - lane;
        const int jh = i + 1 + base + lane;
        const bool offl = (jl < 0)        || (batch[jl] != g);
        const bool offh = (jh >= N_NODES) || (batch[jh] != g);
        const unsigned ml = __ballot_sync(0xffffffffu, offl);
        const unsigned mh = __ballot_sync(0xffffffffu, offh);
        if (seg_lo < 0 && ml) seg_lo = i - base - (__ffs(ml) - 1);
        if (seg_hi < 0 && mh) seg_hi = i + 1 + base + (__ffs(mh) - 1);
    }

    const float xi = pos[3 * i + 0];
    const float yi = pos[3 * i + 1];
    const float zi = pos[3 * i + 2];
    // sq exactly as jnp.sum(pos*pos, -1): (x*x + y*y) + z*z, no FMA contraction
    const float sqi = __fadd_rn(__fadd_rn(__fmul_rn(xi, xi), __fmul_rn(yi, yi)),
                                __fmul_rn(zi, zi));

    // ---- gather valid candidates via ballot-prefix append (no atomics) ----
    int cnt = 0;                                            // lane-uniform
    for (int jb = seg_lo; jb < seg_hi && cnt < CAND; jb += 32) {
        const int j = jb + lane;
        bool valid = (j < seg_hi) && (j != i);
        float d2 = 0.0f;
        if (valid) {
            const float xj = pos[3 * j + 0];
            const float yj = pos[3 * j + 1];
            const float zj = pos[3 * j + 2];
            const float sqj = __fadd_rn(__fadd_rn(__fmul_rn(xj, xj), __fmul_rn(yj, yj)),
                                        __fmul_rn(zj, zj));
            const float dot = __fadd_rn(__fadd_rn(__fmul_rn(xi, xj), __fmul_rn(yi, yj)),
                                        __fmul_rn(zi, zj));
            d2 = __fsub_rn(__fadd_rn(sqi, sqj), __fmul_rn(2.0f, dot));
            d2 = fmaxf(d2, 0.0f);
            valid = (d2 <= CUTOFF2);
        }
        const unsigned m = __ballot_sync(0xffffffffu, valid);
        if (valid) {
            const int pos_c = cnt + __popc(m & ((1u << lane) - 1u));
            if (pos_c < CAND) {
                s_key[w][pos_c] = ((unsigned long long)__float_as_uint(d2) << 32)
                                  | (unsigned)j;
            }
        }
        cnt += __popc(m);
    }
    __syncwarp();
    const int C = cnt < CAND ? cnt : CAND;

    const int NK = N_NODES * K;
    float* __restrict__ out_row = out;
    float* __restrict__ out_col = out + NK;
    float* __restrict__ out_w   = out + 2 * NK;
    float* __restrict__ out_m   = out + 3 * NK;
    const int base = i * K;

    // row is always i; padded slots (rank >= min(C,K)) get col=i, w=0, m=0
    out_row[base + lane] = (float)i;
    const int Cc = C < K ? C : K;
    if (lane >= Cc) {
        out_col[base + lane] = (float)i;
        out_w  [base + lane] = 0.0f;
        out_m  [base + lane] = 0.0f;
    }

    // ---- rank candidates by 64-bit key (d2 asc, idx asc); write top-K slots ----
    for (int c = lane; c < C; c += 32) {
        const unsigned long long kc = s_key[w][c];
        int rank = 0;
        #pragma unroll 8
        for (int m = 0; m < C; m++) {
            rank += (s_key[w][m] < kc);
        }
        if (rank < K) {
            const float d2c = __uint_as_float((unsigned)(kc >> 32));
            const int   jc  = (int)(unsigned)(kc & 0xffffffffu);
            out_col[base + rank] = (float)jc;
            out_w  [base + rank] = sqrtf(d2c);
            out_m  [base + rank] = 1.0f;
        }
    }
}

extern "C" void kernel_launch(void* const* d_in, const int* in_sizes, int n_in,
                              void* d_out, int out_size) {
    const float* pos   = (const float*)d_in[0];
    const int*   batch = (const int*)d_in[1];
    float*       out   = (float*)d_out;

    const int blocks = N_NODES / WPB;   // 4096
    radius_graph_kernel<<<blocks, WPB * 32>>>(pos, batch, out);
}